// round 8
// baseline (speedup 1.0000x reference)
#include <cuda_runtime.h>
#include <cuda_bf16.h>
#include <math.h>

#define NMAX 100000
#define EMAX 1000000
#define HID 128

// ---------------- scratch (device globals; no runtime allocation) ------------
__device__ __align__(16) int   g_cnt[NMAX];
__device__ __align__(16) int   g_off[NMAX + 1];
__device__ __align__(16) int   g_cur[NMAX];
__device__ __align__(16) float g_dinv[NMAX];
__device__ __align__(16) int   g_col[EMAX];
__device__ __align__(16) float g_w[EMAX];
__device__ __align__(16) float g_buf1[(size_t)NMAX * HID];
__device__ __align__(16) float g_buf2[(size_t)NMAX * HID];
__device__ __align__(16) int   g_bsums[64];
__device__ int g_is64;

static inline int ceil_div(int a, int b) { return (a + b - 1) / b; }

// ---------------- f32x2 packed math helpers ----------------------------------
__device__ __forceinline__ unsigned long long ffma2(unsigned long long a,
                                                    unsigned long long b,
                                                    unsigned long long c) {
    unsigned long long d;
    asm("fma.rn.f32x2 %0, %1, %2, %3;" : "=l"(d) : "l"(a), "l"(b), "l"(c));
    return d;
}
__device__ __forceinline__ unsigned long long pack2(float lo, float hi) {
    unsigned long long d;
    asm("mov.b64 %0, {%1, %2};" : "=l"(d) : "r"(__float_as_uint(lo)), "r"(__float_as_uint(hi)));
    return d;
}
__device__ __forceinline__ float2 unpack2(unsigned long long v) {
    unsigned int lo, hi;
    asm("mov.b64 {%0, %1}, %2;" : "=r"(lo), "=r"(hi) : "l"(v));
    return make_float2(__uint_as_float(lo), __uint_as_float(hi));
}

// index loader that works for int32 or int64 edge_index
__device__ __forceinline__ int load_idx(const void* p, int is64, long long i) {
    if (is64) return (int)((const long long*)p)[i];
    return ((const int*)p)[i];
}

// ---------------- dtype detection --------------------------------------------
__global__ void k_detect(const int* __restrict__ p, int nwords) {
    bool oddzero = true;
    for (int i = threadIdx.x; i < 1024; i += 32) {
        int w = 2 * i + 1;
        if (w < nwords && p[w] != 0) oddzero = false;
    }
    oddzero = __all_sync(0xffffffffu, oddzero);
    if (threadIdx.x == 0) g_is64 = oddzero ? 1 : 0;
}

// ---------------- preprocessing ----------------------------------------------
__global__ void k_zero_cnt(int n) {
    int i = blockIdx.x * blockDim.x + threadIdx.x;
    if (i < n) g_cnt[i] = 0;
}

__global__ void k_hist(const void* __restrict__ ei, int ne, int n) {
    int e = blockIdx.x * blockDim.x + threadIdx.x;
    int is64 = g_is64;
    if (e < ne) {
        int d = load_idx(ei, is64, (long long)ne + e);
        if (d >= 0 && d < n) atomicAdd(&g_cnt[d], 1);
    }
}

__global__ void k_scan1(int n) {
    __shared__ int sh[256];
    int tid  = threadIdx.x;
    int base = blockIdx.x * 2048;
    int vals[8];
    int tsum = 0;
#pragma unroll
    for (int v = 0; v < 8; v++) {
        int idx = base + tid * 8 + v;
        vals[v] = (idx < n) ? g_cnt[idx] : 0;
        tsum += vals[v];
    }
    sh[tid] = tsum;
    __syncthreads();
    for (int s = 1; s < 256; s <<= 1) {
        int t = (tid >= s) ? sh[tid - s] : 0;
        __syncthreads();
        sh[tid] += t;
        __syncthreads();
    }
    int run = sh[tid] - tsum;
    if (tid == 255) g_bsums[blockIdx.x] = sh[255];
#pragma unroll
    for (int v = 0; v < 8; v++) {
        int idx = base + tid * 8 + v;
        if (idx < n) g_off[idx] = run;
        run += vals[v];
    }
}

__global__ void k_scan2(int nb) {
    if (threadIdx.x == 0 && blockIdx.x == 0) {
        int run = 0;
        for (int b = 0; b < nb; b++) {
            int t = g_bsums[b];
            g_bsums[b] = run;
            run += t;
        }
    }
}

__global__ void k_scan3(int n, int ne) {
    int i = blockIdx.x * blockDim.x + threadIdx.x;
    if (i < n) {
        int o = g_off[i] + g_bsums[i >> 11];
        g_off[i] = o;
        g_cur[i] = o;
        g_dinv[i] = rsqrtf((float)(g_cnt[i] + 1));  // +1 self loop
        if (i == 0) g_off[n] = ne;
    }
}

__global__ void k_fill(const void* __restrict__ ei, int ne, int n) {
    int e = blockIdx.x * blockDim.x + threadIdx.x;
    int is64 = g_is64;
    if (e < ne) {
        int s = load_idx(ei, is64, e);
        int d = load_idx(ei, is64, (long long)ne + e);
        if (s >= 0 && s < n && d >= 0 && d < n) {
            int p = atomicAdd(&g_cur[d], 1);
            g_col[p] = s;
            g_w[p]   = g_dinv[s] * g_dinv[d];
        }
    }
}

// ------- aggregation (no bias/relu): Out[i] = sum norm_ij * X[j] + dinv_i^2 X[i]
template <int F, int SRC, int DST>
__global__ void k_agg(const float* __restrict__ Xext, int n) {
    const float* X = (SRC == 0) ? Xext : (SRC == 1 ? g_buf1 : g_buf2);
    float* O       = (DST == 1) ? g_buf1 : g_buf2;
    int lane = threadIdx.x & 31, warp = threadIdx.x >> 5;
    int i = blockIdx.x * 8 + warp;
    if (i >= n) return;
    int e0 = g_off[i], e1 = g_off[i + 1];
    float di = g_dinv[i];
    float sw = di * di;

    if (F == 64) {
        float2 acc = make_float2(0.f, 0.f);
        for (int e = e0; e < e1; e++) {
            int s = g_col[e];
            float wv = g_w[e];
            float2 hv = ((const float2*)(X + (size_t)s * 64))[lane];
            acc.x = fmaf(wv, hv.x, acc.x);
            acc.y = fmaf(wv, hv.y, acc.y);
        }
        float2 hs = ((const float2*)(X + (size_t)i * 64))[lane];
        acc.x = fmaf(sw, hs.x, acc.x);
        acc.y = fmaf(sw, hs.y, acc.y);
        ((float2*)(O + (size_t)i * 64))[lane] = acc;
    } else {
        float4 acc = make_float4(0.f, 0.f, 0.f, 0.f);
        for (int e = e0; e < e1; e++) {
            int s = g_col[e];
            float wv = g_w[e];
            float4 hv = ((const float4*)(X + (size_t)s * 128))[lane];
            acc.x = fmaf(wv, hv.x, acc.x);
            acc.y = fmaf(wv, hv.y, acc.y);
            acc.z = fmaf(wv, hv.z, acc.z);
            acc.w = fmaf(wv, hv.w, acc.w);
        }
        float4 hs = ((const float4*)(X + (size_t)i * 128))[lane];
        acc.x = fmaf(sw, hs.x, acc.x);
        acc.y = fmaf(sw, hs.y, acc.y);
        acc.z = fmaf(sw, hs.z, acc.z);
        acc.w = fmaf(sw, hs.w, acc.w);
        ((float4*)(O + (size_t)i * 128))[lane] = acc;
    }
}

// ------- GEMM + bias + relu: O[n,128] = relu(X[n,K] @ W[K,128] + b) ----------
// FFMA2, issue-lean: block = 128 rows = 64 row-pairs, 8 warps, warp = 8 pairs.
// X staged as float4 {r0[k],r1[k],r0[k+1],r1[k+1]} -> 1 broadcast LDS.128 feeds
// two packed-k FFMA2 operands.
template <int K, int SRC, int DST>
__global__ void k_gemm(const float* __restrict__ W, const float* __restrict__ bias, int n) {
    constexpr int CH = 32;
    __shared__ __align__(16) float  Wc[CH * 128];     // 16KB
    __shared__ __align__(16) float4 Xp4[64 * (CH/2)]; // 16KB: pair x kk(=k/2)
    const float* X = (SRC == 1) ? g_buf1 : g_buf2;
    float* O       = (DST == 1) ? g_buf1 : g_buf2;

    int tid = threadIdx.x, lane = tid & 31, warp = tid >> 5;
    int rb = blockIdx.x * 128;
    int pairbase = warp * 8;

    unsigned long long acc[8][4];
#pragma unroll
    for (int p = 0; p < 8; p++)
#pragma unroll
        for (int c = 0; c < 4; c++) acc[p][c] = 0ull;

    for (int c0 = 0; c0 < K; c0 += CH) {
        __syncthreads();
        // stage W chunk: CH*128 floats = 1024 float4
        {
            const float4* Wg4 = (const float4*)(W + c0 * 128);
            float4* Wc4 = (float4*)Wc;
#pragma unroll
            for (int i = 0; i < 4; i++) Wc4[tid + 256 * i] = Wg4[tid + 256 * i];
        }
        // stage X: half-warp per pair; lanes 0-15 -> pair 2pp, 16-31 -> 2pp+1.
        // kk = lane&15 covers CH/2 = 16 packed-k slots; float2 loads coalesced.
        {
            int half = lane >> 4, kk = lane & 15;
#pragma unroll
            for (int pp = 0; pp < 4; pp++) {
                int p = warp * 8 + 2 * pp + half;
                int r0 = rb + 2 * p;
                float2 a = (r0 < n)     ? ((const float2*)(X + (size_t)r0 * K + c0))[kk]       : make_float2(0.f, 0.f);
                float2 b = (r0 + 1 < n) ? ((const float2*)(X + (size_t)(r0 + 1) * K + c0))[kk] : make_float2(0.f, 0.f);
                Xp4[p * (CH/2) + kk] = make_float4(a.x, b.x, a.y, b.y);
            }
        }
        __syncthreads();

        const float4* Wc4 = (const float4*)Wc;
#pragma unroll
        for (int kk = 0; kk < CH / 2; kk++) {
            float4 wa = Wc4[(2 * kk) * 32 + lane];
            float4 wb = Wc4[(2 * kk + 1) * 32 + lane];
            unsigned long long wa0 = pack2(wa.x, wa.x), wa1 = pack2(wa.y, wa.y);
            unsigned long long wa2 = pack2(wa.z, wa.z), wa3 = pack2(wa.w, wa.w);
            unsigned long long wb0 = pack2(wb.x, wb.x), wb1 = pack2(wb.y, wb.y);
            unsigned long long wb2 = pack2(wb.z, wb.z), wb3 = pack2(wb.w, wb.w);
#pragma unroll
            for (int p = 0; p < 8; p++) {
                ulonglong2 xu = ((const ulonglong2*)&Xp4[(pairbase + p) * (CH/2) + kk])[0];
                acc[p][0] = ffma2(xu.x, wa0, acc[p][0]);
                acc[p][1] = ffma2(xu.x, wa1, acc[p][1]);
                acc[p][2] = ffma2(xu.x, wa2, acc[p][2]);
                acc[p][3] = ffma2(xu.x, wa3, acc[p][3]);
                acc[p][0] = ffma2(xu.y, wb0, acc[p][0]);
                acc[p][1] = ffma2(xu.y, wb1, acc[p][1]);
                acc[p][2] = ffma2(xu.y, wb2, acc[p][2]);
                acc[p][3] = ffma2(xu.y, wb3, acc[p][3]);
            }
        }
    }

    // epilogue: bias + relu, float4 stores
    float4 bv = *(const float4*)&bias[4 * lane];
#pragma unroll
    for (int p = 0; p < 8; p++) {
        float2 u0 = unpack2(acc[p][0]);
        float2 u1 = unpack2(acc[p][1]);
        float2 u2 = unpack2(acc[p][2]);
        float2 u3 = unpack2(acc[p][3]);
        int r0 = rb + 2 * (pairbase + p);
        float4 oe = make_float4(fmaxf(u0.x + bv.x, 0.f), fmaxf(u1.x + bv.y, 0.f),
                                fmaxf(u2.x + bv.z, 0.f), fmaxf(u3.x + bv.w, 0.f));
        float4 oo = make_float4(fmaxf(u0.y + bv.x, 0.f), fmaxf(u1.y + bv.y, 0.f),
                                fmaxf(u2.y + bv.z, 0.f), fmaxf(u3.y + bv.w, 0.f));
        if (r0 < n)     ((float4*)(O + (size_t)r0 * 128))[lane] = oe;
        if (r0 + 1 < n) ((float4*)(O + (size_t)(r0 + 1) * 128))[lane] = oo;
    }
}

// ---------------- head: out = log_softmax(H @ Wl + bl) -----------------------
__global__ void k_final(const float* __restrict__ Wl, const float* __restrict__ bl,
                        float* __restrict__ out, int n) {
    __shared__ __align__(16) float Wt[10 * 128];  // transposed: [j][k]
    __shared__ float bls[10];
    int tid = threadIdx.x;
    for (int idx = tid; idx < 1280; idx += 256) {
        int k = idx / 10, j = idx - 10 * k;
        Wt[j * 128 + k] = Wl[idx];
    }
    if (tid < 10) bls[tid] = bl[tid];
    __syncthreads();

    int lane = tid & 31, warp = tid >> 5;
    int i = blockIdx.x * 8 + warp;
    if (i >= n) return;
    float4 hv = ((const float4*)(g_buf2 + (size_t)i * HID))[lane];
    float lg[10];
#pragma unroll
    for (int j = 0; j < 10; j++) {
        float4 wv = ((const float4*)(Wt + j * 128))[lane];
        float p = hv.x * wv.x + hv.y * wv.y + hv.z * wv.z + hv.w * wv.w;
#pragma unroll
        for (int o = 16; o; o >>= 1) p += __shfl_xor_sync(0xffffffffu, p, o);
        lg[j] = p + bls[j];
    }
    float m = lg[0];
#pragma unroll
    for (int j = 1; j < 10; j++) m = fmaxf(m, lg[j]);
    float s = 0.f;
#pragma unroll
    for (int j = 0; j < 10; j++) s += expf(lg[j] - m);
    float lse = m + logf(s);
    if (lane < 10) out[(size_t)i * 10 + lane] = lg[lane] - lse;
}

// ---------------- launch -----------------------------------------------------
extern "C" void kernel_launch(void* const* d_in, const int* in_sizes, int n_in,
                              void* d_out, int out_size) {
    const float* x  = (const float*)d_in[0];
    const void*  ei = d_in[1];
    const float* W1 = (const float*)d_in[2];
    const float* b1 = (const float*)d_in[3];
    const float* W2 = (const float*)d_in[4];
    const float* b2 = (const float*)d_in[5];
    const float* Wl = (const float*)d_in[6];
    const float* bl = (const float*)d_in[7];
    float* out = (float*)d_out;

    int N = in_sizes[0] / 64;
    int E = in_sizes[1] / 2;

    // --- detect edge_index dtype, build normalized CSR ---
    k_detect<<<1, 32>>>((const int*)ei, 2 * E >= 2048 ? 2048 : 2 * E);
    k_zero_cnt<<<ceil_div(N, 256), 256>>>(N);
    k_hist<<<ceil_div(E, 256), 256>>>(ei, E, N);
    int nb = ceil_div(N, 2048);
    k_scan1<<<nb, 256>>>(N);
    k_scan2<<<1, 32>>>(nb);
    k_scan3<<<ceil_div(N, 256), 256>>>(N, E);
    k_fill<<<ceil_div(E, 256), 256>>>(ei, E, N);

    // --- layer 1 (agg-first; A(XW) = (AX)W): agg x (64) -> buf1; gemm -> buf2
    k_agg<64, 0, 1><<<ceil_div(N, 8), 256>>>(x, N);
    k_gemm<64, 1, 2><<<ceil_div(N, 128), 256>>>(W1, b1, N);

    // --- layer 2: agg buf2 (128) -> buf1; gemm -> buf2
    k_agg<128, 2, 1><<<ceil_div(N, 8), 256>>>(nullptr, N);
    k_gemm<128, 1, 2><<<ceil_div(N, 128), 256>>>(W2, b2, N);

    // --- head + log_softmax ---
    k_final<<<ceil_div(N, 8), 256>>>(Wl, bl, out, N);
}

// round 11
// speedup vs baseline: 1.6326x; 1.6326x over previous
#include <cuda_runtime.h>
#include <cuda_bf16.h>
#include <math.h>
#include <cstdint>

#define NMAX 100000
#define EMAX 1000000
#define HID 128

// ---------------- scratch (device globals; no runtime allocation) ------------
__device__ __align__(16) int   g_cnt[NMAX];
__device__ __align__(16) int   g_off[NMAX + 1];
__device__ __align__(16) int   g_cur[NMAX];
__device__ __align__(16) float g_dinv[NMAX];
__device__ __align__(16) int   g_col[EMAX];
__device__ __align__(16) float g_w[EMAX];
__device__ __align__(16) float g_buf1[(size_t)NMAX * HID];
__device__ __align__(16) float g_buf2[(size_t)NMAX * HID];
__device__ __align__(16) int   g_bsums[64];
__device__ int g_is64;

static inline int ceil_div(int a, int b) { return (a + b - 1) / b; }

// ---------------- helpers ----------------------------------------------------
__device__ __forceinline__ int load_idx(const void* p, int is64, long long i) {
    if (is64) return (int)((const long long*)p)[i];
    return ((const int*)p)[i];
}

// split a float2 (two consecutive k) into packed bf16x2 hi and lo words
__device__ __forceinline__ void split2(float2 v, uint32_t& hi, uint32_t& lo) {
    __nv_bfloat16 hx = __float2bfloat16(v.x), hy = __float2bfloat16(v.y);
    float rx = v.x - __bfloat162float(hx);
    float ry = v.y - __bfloat162float(hy);
    __nv_bfloat16 lx = __float2bfloat16(rx), ly = __float2bfloat16(ry);
    hi = ((uint32_t)__bfloat16_as_ushort(hy) << 16) | (uint32_t)__bfloat16_as_ushort(hx);
    lo = ((uint32_t)__bfloat16_as_ushort(ly) << 16) | (uint32_t)__bfloat16_as_ushort(lx);
}

__device__ __forceinline__ void mma_bf16(float& c0, float& c1, float& c2, float& c3,
                                         uint32_t a0, uint32_t a1, uint32_t a2, uint32_t a3,
                                         uint32_t b0, uint32_t b1) {
    asm volatile(
        "mma.sync.aligned.m16n8k16.row.col.f32.bf16.bf16.f32 "
        "{%0,%1,%2,%3}, {%4,%5,%6,%7}, {%8,%9}, {%0,%1,%2,%3};"
        : "+f"(c0), "+f"(c1), "+f"(c2), "+f"(c3)
        : "r"(a0), "r"(a1), "r"(a2), "r"(a3), "r"(b0), "r"(b1));
}

// ---------------- dtype detection --------------------------------------------
__global__ void k_detect(const int* __restrict__ p, int nwords) {
    bool oddzero = true;
    for (int i = threadIdx.x; i < 1024; i += 32) {
        int w = 2 * i + 1;
        if (w < nwords && p[w] != 0) oddzero = false;
    }
    oddzero = __all_sync(0xffffffffu, oddzero);
    if (threadIdx.x == 0) g_is64 = oddzero ? 1 : 0;
}

// ---------------- preprocessing ----------------------------------------------
__global__ void k_zero_cnt(int n) {
    int i = blockIdx.x * blockDim.x + threadIdx.x;
    if (i < n) g_cnt[i] = 0;
}

__global__ void k_hist(const void* __restrict__ ei, int ne, int n) {
    int e = blockIdx.x * blockDim.x + threadIdx.x;
    int is64 = g_is64;
    if (e < ne) {
        int d = load_idx(ei, is64, (long long)ne + e);
        if (d >= 0 && d < n) atomicAdd(&g_cnt[d], 1);
    }
}

__global__ void k_scan1(int n) {
    __shared__ int sh[256];
    int tid  = threadIdx.x;
    int base = blockIdx.x * 2048;
    int vals[8];
    int tsum = 0;
#pragma unroll
    for (int v = 0; v < 8; v++) {
        int idx = base + tid * 8 + v;
        vals[v] = (idx < n) ? g_cnt[idx] : 0;
        tsum += vals[v];
    }
    sh[tid] = tsum;
    __syncthreads();
    for (int s = 1; s < 256; s <<= 1) {
        int t = (tid >= s) ? sh[tid - s] : 0;
        __syncthreads();
        sh[tid] += t;
        __syncthreads();
    }
    int run = sh[tid] - tsum;
    if (tid == 255) g_bsums[blockIdx.x] = sh[255];
#pragma unroll
    for (int v = 0; v < 8; v++) {
        int idx = base + tid * 8 + v;
        if (idx < n) g_off[idx] = run;
        run += vals[v];
    }
}

__global__ void k_scan2(int nb) {
    if (threadIdx.x == 0 && blockIdx.x == 0) {
        int run = 0;
        for (int b = 0; b < nb; b++) {
            int t = g_bsums[b];
            g_bsums[b] = run;
            run += t;
        }
    }
}

__global__ void k_scan3(int n, int ne) {
    int i = blockIdx.x * blockDim.x + threadIdx.x;
    if (i < n) {
        int o = g_off[i] + g_bsums[i >> 11];
        g_off[i] = o;
        g_cur[i] = o;
        g_dinv[i] = rsqrtf((float)(g_cnt[i] + 1));  // +1 self loop
        if (i == 0) g_off[n] = ne;
    }
}

__global__ void k_fill(const void* __restrict__ ei, int ne, int n) {
    int e = blockIdx.x * blockDim.x + threadIdx.x;
    int is64 = g_is64;
    if (e < ne) {
        int s = load_idx(ei, is64, e);
        int d = load_idx(ei, is64, (long long)ne + e);
        if (s >= 0 && s < n && d >= 0 && d < n) {
            int p = atomicAdd(&g_cur[d], 1);
            g_col[p] = s;
            g_w[p]   = g_dinv[s] * g_dinv[d];
        }
    }
}

// ------- aggregation (no bias/relu): Out[i] = sum norm_ij * X[j] + dinv_i^2 X[i]
template <int F, int SRC, int DST>
__global__ void k_agg(const float* __restrict__ Xext, int n) {
    const float* X = (SRC == 0) ? Xext : (SRC == 1 ? g_buf1 : g_buf2);
    float* O       = (DST == 1) ? g_buf1 : g_buf2;
    int lane = threadIdx.x & 31, warp = threadIdx.x >> 5;
    int i = blockIdx.x * 8 + warp;
    if (i >= n) return;
    int e0 = g_off[i], e1 = g_off[i + 1];
    float di = g_dinv[i];
    float sw = di * di;

    if (F == 64) {
        float2 acc = make_float2(0.f, 0.f);
        for (int e = e0; e < e1; e++) {
            int s = g_col[e];
            float wv = g_w[e];
            float2 hv = ((const float2*)(X + (size_t)s * 64))[lane];
            acc.x = fmaf(wv, hv.x, acc.x);
            acc.y = fmaf(wv, hv.y, acc.y);
        }
        float2 hs = ((const float2*)(X + (size_t)i * 64))[lane];
        acc.x = fmaf(sw, hs.x, acc.x);
        acc.y = fmaf(sw, hs.y, acc.y);
        ((float2*)(O + (size_t)i * 64))[lane] = acc;
    } else {
        float4 acc = make_float4(0.f, 0.f, 0.f, 0.f);
        for (int e = e0; e < e1; e++) {
            int s = g_col[e];
            float wv = g_w[e];
            float4 hv = ((const float4*)(X + (size_t)s * 128))[lane];
            acc.x = fmaf(wv, hv.x, acc.x);
            acc.y = fmaf(wv, hv.y, acc.y);
            acc.z = fmaf(wv, hv.z, acc.z);
            acc.w = fmaf(wv, hv.w, acc.w);
        }
        float4 hs = ((const float4*)(X + (size_t)i * 128))[lane];
        acc.x = fmaf(sw, hs.x, acc.x);
        acc.y = fmaf(sw, hs.y, acc.y);
        acc.z = fmaf(sw, hs.z, acc.z);
        acc.w = fmaf(sw, hs.w, acc.w);
        ((float4*)(O + (size_t)i * 128))[lane] = acc;
    }
}

// ------- bf16 split-precision tensor-core GEMM + bias + relu -----------------
// O[n,128] = relu(X[n,K] @ W[K,128] + b)
// CTA: 128 rows x 128 cols; 8 warps = 4(m) x 2(n); warp tile 32x64.
// mma.sync m16n8k16 bf16, 3 MMAs per frag pair (hi*hi, hi*lo, lo*hi).
// K chunked by 32; smem holds packed bf16x2 hi/lo tiles, stride 17 (no conflicts).
template <int K, int SRC, int DST>
__global__ void __launch_bounds__(256)
k_gemm_mma(const float* __restrict__ W, const float* __restrict__ bias, int n) {
    __shared__ uint32_t XsHi[128 * 17], XsLo[128 * 17];  // [row][kk] kk=k/2, 16 slots
    __shared__ uint32_t WsHi[128 * 17], WsLo[128 * 17];  // [col n][kk]

    const float* X = (SRC == 1) ? g_buf1 : g_buf2;
    float* O       = (DST == 1) ? g_buf1 : g_buf2;

    int tid = threadIdx.x, lane = tid & 31, warp = tid >> 5;
    int g = lane >> 2, t = lane & 3;     // mma group / thread-in-group
    int warp_m = warp & 3, warp_n = warp >> 2;
    int rb = blockIdx.x * 128;

    float c[2][8][4];
#pragma unroll
    for (int mi = 0; mi < 2; mi++)
#pragma unroll
        for (int nb = 0; nb < 8; nb++)
#pragma unroll
            for (int q = 0; q < 4; q++) c[mi][nb][q] = 0.f;

    const int NCH = K / 32;
    for (int ch = 0; ch < NCH; ch++) {
        int c0 = ch * 32;
        __syncthreads();
        // stage X chunk: [128 rows][16 kk]; idx = r*16 + kk (coalesced float2 over kk)
        for (int idx = tid; idx < 128 * 16; idx += 256) {
            int r = idx >> 4, kk = idx & 15;
            int row = rb + r;
            float2 v = (row < n) ? *(const float2*)(X + (size_t)row * K + c0 + 2 * kk)
                                 : make_float2(0.f, 0.f);
            uint32_t hi, lo;
            split2(v, hi, lo);
            XsHi[r * 17 + kk] = hi;
            XsLo[r * 17 + kk] = lo;
        }
        // stage W chunk transposed: Ws[n][kk] = {W[c0+2kk][n], W[c0+2kk+1][n]}
        // idx = kk*128 + nn (coalesced over nn)
        for (int idx = tid; idx < 128 * 16; idx += 256) {
            int kk = idx >> 7, nn = idx & 127;
            float2 v;
            v.x = W[(size_t)(c0 + 2 * kk) * 128 + nn];
            v.y = W[(size_t)(c0 + 2 * kk + 1) * 128 + nn];
            uint32_t hi, lo;
            split2(v, hi, lo);
            WsHi[nn * 17 + kk] = hi;
            WsLo[nn * 17 + kk] = lo;
        }
        __syncthreads();

#pragma unroll
        for (int step = 0; step < 2; step++) {
            int kb = step * 8;
            uint32_t bh0[8], bh1[8], bl0[8], bl1[8];
#pragma unroll
            for (int nb = 0; nb < 8; nb++) {
                int nl = warp_n * 64 + nb * 8 + g;
                bh0[nb] = WsHi[nl * 17 + kb + t];
                bh1[nb] = WsHi[nl * 17 + kb + t + 4];
                bl0[nb] = WsLo[nl * 17 + kb + t];
                bl1[nb] = WsLo[nl * 17 + kb + t + 4];
            }
#pragma unroll
            for (int mi = 0; mi < 2; mi++) {
                int rl = warp_m * 32 + mi * 16 + g;
                uint32_t ah0 = XsHi[rl * 17 + kb + t];
                uint32_t ah1 = XsHi[(rl + 8) * 17 + kb + t];
                uint32_t ah2 = XsHi[rl * 17 + kb + t + 4];
                uint32_t ah3 = XsHi[(rl + 8) * 17 + kb + t + 4];
                uint32_t al0 = XsLo[rl * 17 + kb + t];
                uint32_t al1 = XsLo[(rl + 8) * 17 + kb + t];
                uint32_t al2 = XsLo[rl * 17 + kb + t + 4];
                uint32_t al3 = XsLo[(rl + 8) * 17 + kb + t + 4];
#pragma unroll
                for (int nb = 0; nb < 8; nb++) {
                    mma_bf16(c[mi][nb][0], c[mi][nb][1], c[mi][nb][2], c[mi][nb][3],
                             ah0, ah1, ah2, ah3, bh0[nb], bh1[nb]);
                    mma_bf16(c[mi][nb][0], c[mi][nb][1], c[mi][nb][2], c[mi][nb][3],
                             ah0, ah1, ah2, ah3, bl0[nb], bl1[nb]);
                    mma_bf16(c[mi][nb][0], c[mi][nb][1], c[mi][nb][2], c[mi][nb][3],
                             al0, al1, al2, al3, bh0[nb], bh1[nb]);
                }
            }
        }
    }

    // epilogue: bias + relu; c0/c1 -> (row g), c2/c3 -> (row g+8), cols 2t,2t+1
#pragma unroll
    for (int mi = 0; mi < 2; mi++) {
        int row0 = rb + warp_m * 32 + mi * 16 + g;
        int row1 = row0 + 8;
#pragma unroll
        for (int nb = 0; nb < 8; nb++) {
            int col = warp_n * 64 + nb * 8 + 2 * t;
            float b0 = bias[col], b1 = bias[col + 1];
            if (row0 < n) {
                float2 o0 = make_float2(fmaxf(c[mi][nb][0] + b0, 0.f),
                                        fmaxf(c[mi][nb][1] + b1, 0.f));
                *(float2*)(O + (size_t)row0 * 128 + col) = o0;
            }
            if (row1 < n) {
                float2 o1 = make_float2(fmaxf(c[mi][nb][2] + b0, 0.f),
                                        fmaxf(c[mi][nb][3] + b1, 0.f));
                *(float2*)(O + (size_t)row1 * 128 + col) = o1;
            }
        }
    }
}

// ---------------- head: out = log_softmax(H @ Wl + bl) -----------------------
__global__ void k_final(const float* __restrict__ Wl, const float* __restrict__ bl,
                        float* __restrict__ out, int n) {
    __shared__ __align__(16) float Wt[10 * 128];  // transposed: [j][k]
    __shared__ float bls[10];
    int tid = threadIdx.x;
    for (int idx = tid; idx < 1280; idx += 256) {
        int k = idx / 10, j = idx - 10 * k;
        Wt[j * 128 + k] = Wl[idx];
    }
    if (tid < 10) bls[tid] = bl[tid];
    __syncthreads();

    int lane = tid & 31, warp = tid >> 5;
    int i = blockIdx.x * 8 + warp;
    if (i >= n) return;
    float4 hv = ((const float4*)(g_buf2 + (size_t)i * HID))[lane];
    float lg[10];
#pragma unroll
    for (int j = 0; j < 10; j++) {
        float4 wv = ((const float4*)(Wt + j * 128))[lane];
        float p = hv.x * wv.x + hv.y * wv.y + hv.z * wv.z + hv.w * wv.w;
#pragma unroll
        for (int o = 16; o; o >>= 1) p += __shfl_xor_sync(0xffffffffu, p, o);
        lg[j] = p + bls[j];
    }
    float m = lg[0];
#pragma unroll
    for (int j = 1; j < 10; j++) m = fmaxf(m, lg[j]);
    float s = 0.f;
#pragma unroll
    for (int j = 0; j < 10; j++) s += expf(lg[j] - m);
    float lse = m + logf(s);
    if (lane < 10) out[(size_t)i * 10 + lane] = lg[lane] - lse;
}

// ---------------- launch -----------------------------------------------------
extern "C" void kernel_launch(void* const* d_in, const int* in_sizes, int n_in,
                              void* d_out, int out_size) {
    const float* x  = (const float*)d_in[0];
    const void*  ei = d_in[1];
    const float* W1 = (const float*)d_in[2];
    const float* b1 = (const float*)d_in[3];
    const float* W2 = (const float*)d_in[4];
    const float* b2 = (const float*)d_in[5];
    const float* Wl = (const float*)d_in[6];
    const float* bl = (const float*)d_in[7];
    float* out = (float*)d_out;

    int N = in_sizes[0] / 64;
    int E = in_sizes[1] / 2;

    // --- detect edge_index dtype, build normalized CSR ---
    k_detect<<<1, 32>>>((const int*)ei, 2 * E >= 2048 ? 2048 : 2 * E);
    k_zero_cnt<<<ceil_div(N, 256), 256>>>(N);
    k_hist<<<ceil_div(E, 256), 256>>>(ei, E, N);
    int nb = ceil_div(N, 2048);
    k_scan1<<<nb, 256>>>(N);
    k_scan2<<<1, 32>>>(nb);
    k_scan3<<<ceil_div(N, 256), 256>>>(N, E);
    k_fill<<<ceil_div(E, 256), 256>>>(ei, E, N);

    // --- layer 1 (agg-first; A(XW) = (AX)W): agg x (64) -> buf1; mma gemm -> buf2
    k_agg<64, 0, 1><<<ceil_div(N, 8), 256>>>(x, N);
    k_gemm_mma<64, 1, 2><<<ceil_div(N, 128), 256>>>(W1, b1, N);

    // --- layer 2: agg buf2 (128) -> buf1; mma gemm -> buf2
    k_agg<128, 2, 1><<<ceil_div(N, 8), 256>>>(nullptr, N);
    k_gemm_mma<128, 1, 2><<<ceil_div(N, 128), 256>>>(W2, b2, N);

    // --- head + log_softmax ---
    k_final<<<ceil_div(N, 8), 256>>>(Wl, bl, out, N);
}